// round 16
// baseline (speedup 1.0000x reference)
#include <cuda_runtime.h>
#include <math.h>
#include <float.h>

// Problem constants
#define Bc    8
#define Fc    16
#define NSc   196
#define Jc    24
#define Hc    8
#define DHc   64
#define DIMc  512
#define ROTc  32
#define Nc    3160          // J + F*NS
#define MROWS (Bc*Nc)       // 25280
#define BHc   64            // B*H
#define NSP   3136          // F*NS
#define SKR   220           // J + NS (spatial key rows)
#define JCH   4             // joints key chunks
#define JKEYS 790           // keys per joints chunk

// -------- scratch (device globals; no runtime allocation) --------
__device__ float g_Q   [(size_t)BHc * Nc  * 64];
__device__ float g_Kraw[(size_t)BHc * Nc  * 64];
__device__ float g_Krope[(size_t)BHc * NSP * 64];
__device__ float g_V   [(size_t)BHc * Nc  * 64];
__device__ float g_AO  [(size_t)MROWS * 512];
__device__ float g_JO  [(size_t)JCH * BHc * 32 * 64];
__device__ float g_Jm  [(size_t)JCH * BHc * 32];
__device__ float g_Jl  [(size_t)JCH * BHc * 32];

// -------- tf32 helpers --------
__device__ __forceinline__ unsigned f2tf32(float x) {
    unsigned u;
    asm("cvt.rna.tf32.f32 %0, %1;" : "=r"(u) : "f"(x));
    return u;
}

__device__ __forceinline__ void mma_tf32(float* d, const unsigned* a, const unsigned* b) {
    asm volatile(
        "mma.sync.aligned.m16n8k8.row.col.f32.tf32.tf32.f32 "
        "{%0,%1,%2,%3}, {%4,%5,%6,%7}, {%8,%9}, {%0,%1,%2,%3};\n"
        : "+f"(d[0]), "+f"(d[1]), "+f"(d[2]), "+f"(d[3])
        : "r"(a[0]), "r"(a[1]), "r"(a[2]), "r"(a[3]),
          "r"(b[0]), "r"(b[1]));
}

// ======== QKV GEMM: 128(M) x 256(N) block, 64x64 warp tile, fused epilogue ========
// 256 threads = 8 warps in 2(m) x 4(n); each warp: 4x8 m16n8k8 tiles per k8.
__global__ __launch_bounds__(256) void qkv_gemm_fused(
        const float* __restrict__ A, const float* __restrict__ Bm,
        const float* __restrict__ sinp, const float* __restrict__ cosp) {
    __shared__ unsigned As[128][20];
    __shared__ unsigned Bs[16][264];
    const int K = 512, N = 1536;

    int tid = threadIdx.x, lane = tid & 31, warp = tid >> 5;
    int wm = warp >> 2, wn = warp & 3;
    int g = lane >> 2, t = lane & 3;
    int row0 = blockIdx.y * 128;
    int col0 = blockIdx.x * 256;

    int arow = tid >> 1, aseg = (tid & 1) * 8;
    int brow = tid >> 4, bcol = (tid & 15) * 4;
    int arowg = min(row0 + arow, MROWS - 1);

    const float* Ap = A + (size_t)arowg * K + aseg;
    const float* Bp = Bm + (size_t)brow * N + col0 + bcol;

    float acc[4][8][4];
    #pragma unroll
    for (int i = 0; i < 4; i++)
        #pragma unroll
        for (int j = 0; j < 8; j++)
            #pragma unroll
            for (int r = 0; r < 4; r++) acc[i][j][r] = 0.f;

    float4 ra0 = *(const float4*)Ap, ra1 = *(const float4*)(Ap + 4);
    float4 rb[4];
    #pragma unroll
    for (int j = 0; j < 4; j++) rb[j] = *(const float4*)(Bp + j * 64);

    for (int k0 = 0; k0 < K; k0 += 16) {
        *(uint4*)&As[arow][aseg] =
            make_uint4(f2tf32(ra0.x), f2tf32(ra0.y), f2tf32(ra0.z), f2tf32(ra0.w));
        *(uint4*)&As[arow][aseg + 4] =
            make_uint4(f2tf32(ra1.x), f2tf32(ra1.y), f2tf32(ra1.z), f2tf32(ra1.w));
        #pragma unroll
        for (int j = 0; j < 4; j++)
            *(uint4*)&Bs[brow][bcol + j * 64] =
                make_uint4(f2tf32(rb[j].x), f2tf32(rb[j].y), f2tf32(rb[j].z), f2tf32(rb[j].w));
        __syncthreads();

        if (k0 + 16 < K) {
            Ap += 16;
            Bp += (size_t)16 * N;
            ra0 = *(const float4*)Ap; ra1 = *(const float4*)(Ap + 4);
            #pragma unroll
            for (int j = 0; j < 4; j++) rb[j] = *(const float4*)(Bp + j * 64);
        }

        #pragma unroll
        for (int kk = 0; kk < 16; kk += 8) {
            unsigned af[4][4], bf[8][2];
            #pragma unroll
            for (int mi = 0; mi < 4; mi++) {
                int r = wm * 64 + mi * 16;
                af[mi][0] = As[r + g][kk + t];
                af[mi][1] = As[r + 8 + g][kk + t];
                af[mi][2] = As[r + g][kk + 4 + t];
                af[mi][3] = As[r + 8 + g][kk + 4 + t];
            }
            #pragma unroll
            for (int nj = 0; nj < 8; nj++) {
                int c = wn * 64 + nj * 8 + g;
                bf[nj][0] = Bs[kk + t][c];
                bf[nj][1] = Bs[kk + 4 + t][c];
            }
            #pragma unroll
            for (int mi = 0; mi < 4; mi++)
                #pragma unroll
                for (int nj = 0; nj < 8; nj++)
                    mma_tf32(acc[mi][nj], af[mi], bf[nj]);
        }
        __syncthreads();
    }

    // fused epilogue: split into Q/K/V head-major with scale + RoPE
    int cbase = col0 + wn * 64;
    #pragma unroll
    for (int mi = 0; mi < 4; mi++) {
        int rbase = row0 + wm * 64 + mi * 16 + g;
        #pragma unroll
        for (int half = 0; half < 2; half++) {
            int r = rbase + half * 8;
            if (r >= MROWS) continue;
            int b = r / Nc, n = r - b * Nc;
            bool sp = (n >= Jc);
            int m = n - Jc;
            int s = sp ? (m % NSc) : 0;
            #pragma unroll
            for (int nj = 0; nj < 8; nj++) {
                int c = cbase + nj * 8 + 2 * t;
                float x = acc[mi][nj][half * 2 + 0];
                float y = acc[mi][nj][half * 2 + 1];
                int which = c >> 9, h = (c >> 6) & 7, d = c & 63;
                int bh = b * 8 + h;
                size_t o = ((size_t)bh * Nc + n) * 64 + d;
                if (which == 0) {          // Q
                    x *= 0.125f; y *= 0.125f;
                    if (sp && d < ROTc) {
                        float c0 = cosp[s * ROTc + d],     s0 = sinp[s * ROTc + d];
                        float c1 = cosp[s * ROTc + d + 1], s1 = sinp[s * ROTc + d + 1];
                        float xo = x * c0 - y * s0;
                        float yo = y * c1 + x * s1;
                        x = xo; y = yo;
                    }
                    *(float2*)(g_Q + o) = make_float2(x, y);
                } else if (which == 1) {   // K
                    *(float2*)(g_Kraw + o) = make_float2(x, y);
                    if (sp) {
                        float xo = x, yo = y;
                        if (d < ROTc) {
                            float c0 = cosp[s * ROTc + d],     s0 = sinp[s * ROTc + d];
                            float c1 = cosp[s * ROTc + d + 1], s1 = sinp[s * ROTc + d + 1];
                            xo = x * c0 - y * s0;
                            yo = y * c1 + x * s1;
                        }
                        *(float2*)(g_Krope + ((size_t)bh * NSP + m) * 64 + d) =
                            make_float2(xo, yo);
                    }
                } else {                   // V
                    *(float2*)(g_V + o) = make_float2(x, y);
                }
            }
        }
    }
}

// ======== generic TF32 GEMM 128x128 (single-buffer + reg prefetch, +bias) ========
__global__ __launch_bounds__(256) void tgemm128(
        const float* __restrict__ A, const float* __restrict__ Bm,
        const float* __restrict__ bias, float* __restrict__ C,
        int M, int N, int K) {
    __shared__ unsigned As[128][20];
    __shared__ unsigned Bs[16][136];

    int tid = threadIdx.x, lane = tid & 31, warp = tid >> 5;
    int wm = warp >> 2, wn = warp & 3;
    int g = lane >> 2, t = lane & 3;
    int row0 = blockIdx.y * 128;
    int col0 = blockIdx.x * 128;

    int arow = tid >> 1, aseg = (tid & 1) * 8;
    int brow = tid >> 4, bseg = (tid & 15) * 8;
    int arowg = min(row0 + arow, M - 1);

    const float* Ap = A + (size_t)arowg * K + aseg;
    const float* Bp = Bm + (size_t)brow * N + col0 + bseg;

    float acc[4][4][4];
    #pragma unroll
    for (int i = 0; i < 4; i++)
        #pragma unroll
        for (int j = 0; j < 4; j++)
            #pragma unroll
            for (int r = 0; r < 4; r++) acc[i][j][r] = 0.f;

    float4 ra0 = *(const float4*)Ap,  ra1 = *(const float4*)(Ap + 4);
    float4 rb0 = *(const float4*)Bp,  rb1 = *(const float4*)(Bp + 4);

    for (int k0 = 0; k0 < K; k0 += 16) {
        *(uint4*)&As[arow][aseg] =
            make_uint4(f2tf32(ra0.x), f2tf32(ra0.y), f2tf32(ra0.z), f2tf32(ra0.w));
        *(uint4*)&As[arow][aseg + 4] =
            make_uint4(f2tf32(ra1.x), f2tf32(ra1.y), f2tf32(ra1.z), f2tf32(ra1.w));
        *(uint4*)&Bs[brow][bseg] =
            make_uint4(f2tf32(rb0.x), f2tf32(rb0.y), f2tf32(rb0.z), f2tf32(rb0.w));
        *(uint4*)&Bs[brow][bseg + 4] =
            make_uint4(f2tf32(rb1.x), f2tf32(rb1.y), f2tf32(rb1.z), f2tf32(rb1.w));
        __syncthreads();

        if (k0 + 16 < K) {
            Ap += 16;
            Bp += (size_t)16 * N;
            ra0 = *(const float4*)Ap;  ra1 = *(const float4*)(Ap + 4);
            rb0 = *(const float4*)Bp;  rb1 = *(const float4*)(Bp + 4);
        }

        #pragma unroll
        for (int kk = 0; kk < 16; kk += 8) {
            unsigned af[4][4], bf[4][2];
            #pragma unroll
            for (int mi = 0; mi < 4; mi++) {
                int r = wm * 64 + mi * 16;
                af[mi][0] = As[r + g][kk + t];
                af[mi][1] = As[r + 8 + g][kk + t];
                af[mi][2] = As[r + g][kk + 4 + t];
                af[mi][3] = As[r + 8 + g][kk + 4 + t];
            }
            #pragma unroll
            for (int nj = 0; nj < 4; nj++) {
                int c = wn * 32 + nj * 8 + g;
                bf[nj][0] = Bs[kk + t][c];
                bf[nj][1] = Bs[kk + 4 + t][c];
            }
            #pragma unroll
            for (int mi = 0; mi < 4; mi++)
                #pragma unroll
                for (int nj = 0; nj < 4; nj++)
                    mma_tf32(acc[mi][nj], af[mi], bf[nj]);
        }
        __syncthreads();
    }

    #pragma unroll
    for (int mi = 0; mi < 4; mi++) {
        #pragma unroll
        for (int nj = 0; nj < 4; nj++) {
            int r = row0 + wm * 64 + mi * 16 + g;
            int c = col0 + wn * 32 + nj * 8 + 2 * t;
            float bb0 = 0.f, bb1 = 0.f;
            if (bias) { bb0 = bias[c]; bb1 = bias[c + 1]; }
            if (r < M)
                *(float2*)(C + (size_t)r * N + c) =
                    make_float2(acc[mi][nj][0] + bb0, acc[mi][nj][1] + bb1);
            if (r + 8 < M)
                *(float2*)(C + (size_t)(r + 8) * N + c) =
                    make_float2(acc[mi][nj][2] + bb0, acc[mi][nj][3] + bb1);
        }
    }
}

// ============ joints attention: split-KV flash (block per (bh, chunk)) ============
__global__ __launch_bounds__(256) void joints_attn_mma() {
    extern __shared__ float smem[];
    unsigned* uK  = (unsigned*)smem;            // 128*68
    unsigned* uVt = uK + 128 * 68;              // 64*132
    unsigned* uQ  = uVt + 64 * 132;             // 64*36
    float*    St  = (float*)(uQ + 64 * 36);     // 128*36
    unsigned* uP  = (unsigned*)(St + 128 * 36); // 32*133
    float*   red  = (float*)(uP + 32 * 133);    // 256
    float*  mrow  = red + 256;                  // 32
    float*   scl  = mrow + 32;                  // 32
    float*  lrow  = scl + 32;                   // 32

    int bh = blockIdx.x;
    int chunk = blockIdx.y;
    int kb = chunk * JKEYS;
    int tid = threadIdx.x, lane = tid & 31, warp = tid >> 5;
    int g = lane >> 2, t = lane & 3;

    const float* Kb = g_Kraw + (size_t)bh * Nc * 64;
    const float* Vb = g_V    + (size_t)bh * Nc * 64;

    if (tid < 32) { mrow[tid] = -FLT_MAX; lrow[tid] = 0.f; }

    for (int i = tid; i < 32 * 64; i += 256) {
        int q = i >> 6, d = i & 63;
        int qq = (q < Jc) ? q : (Jc - 1);
        uQ[d * 36 + q] = f2tf32(g_Q[((size_t)bh * Nc + qq) * 64 + d]);
    }

    float oc[2][4] = {{0,0,0,0},{0,0,0,0}};

    for (int c0 = 0; c0 < JKEYS; c0 += 128) {
        int kn = min(128, JKEYS - c0);
        __syncthreads();
        for (int i = tid; i < 128 * 64; i += 256) {
            int r = i >> 6, d = i & 63;
            float kv = 0.f, vv = 0.f;
            if (r < kn) {
                kv = Kb[(size_t)(kb + c0 + r) * 64 + d];
                vv = Vb[(size_t)(kb + c0 + r) * 64 + d];
            }
            uK[r * 68 + d]   = f2tf32(kv);
            uVt[d * 132 + r] = f2tf32(vv);
        }
        __syncthreads();

        for (int tIdx = warp; tIdx < 32; tIdx += 8) {
            int mi = tIdx & 7, ni = tIdx >> 3;
            if (mi * 16 >= kn + 15) continue;
            float c[4] = {0,0,0,0};
            #pragma unroll
            for (int kk = 0; kk < 8; kk++) {
                unsigned a[4], bfr[2];
                const unsigned* Ab = uK + (mi * 16) * 68 + kk * 8;
                a[0] = Ab[g * 68 + t];       a[1] = Ab[(g + 8) * 68 + t];
                a[2] = Ab[g * 68 + 4 + t];   a[3] = Ab[(g + 8) * 68 + 4 + t];
                const unsigned* Bb = uQ + (kk * 8) * 36 + ni * 8;
                bfr[0] = Bb[t * 36 + g];     bfr[1] = Bb[(4 + t) * 36 + g];
                mma_tf32(c, a, bfr);
            }
            float* Sb = St + (mi * 16) * 36 + ni * 8;
            *(float2*)(Sb + g * 36 + 2 * t)       = make_float2(c[0], c[1]);
            *(float2*)(Sb + (g + 8) * 36 + 2 * t) = make_float2(c[2], c[3]);
        }
        __syncthreads();

        {
            int q = tid & 31, s = tid >> 5;
            int j0 = s * 16, j1 = min(j0 + 16, kn);
            float lm = -FLT_MAX;
            for (int j = j0; j < j1; j++) lm = fmaxf(lm, St[j * 36 + q]);
            red[s * 32 + q] = lm;
            __syncthreads();
            float cm = red[q];
            #pragma unroll
            for (int ss = 1; ss < 8; ss++) cm = fmaxf(cm, red[ss * 32 + q]);
            float mold = mrow[q];
            float mnew = fmaxf(mold, cm);
            __syncthreads();
            float ls = 0.f;
            for (int j = j0; j < j1; j++) {
                float e = __expf(St[j * 36 + q] - mnew);
                ls += e;
                uP[q * 133 + j] = f2tf32(e);
            }
            for (int j = j1; j < j0 + 16; j++) uP[q * 133 + j] = 0u;
            red[s * 32 + q] = ls;
            __syncthreads();
            if (s == 0) {
                float tot = 0.f;
                #pragma unroll
                for (int ss = 0; ss < 8; ss++) tot += red[ss * 32 + q];
                float sc = __expf(mold - mnew);
                lrow[q] = lrow[q] * sc + tot;
                mrow[q] = mnew;
                scl[q]  = sc;
            }
        }
        __syncthreads();

        #pragma unroll
        for (int ti = 0; ti < 2; ti++) {
            int tIdx = warp + ti * 8;
            int mi = tIdx & 1, ni = tIdx >> 1;
            int q = mi * 16 + g;
            float s0 = scl[q], s1 = scl[q + 8];
            oc[ti][0] *= s0; oc[ti][1] *= s0; oc[ti][2] *= s1; oc[ti][3] *= s1;
            for (int kk = 0; kk < 16; kk++) {
                unsigned a[4], bfr[2];
                const unsigned* Ab = uP + (mi * 16) * 133 + kk * 8;
                a[0] = Ab[g * 133 + t];      a[1] = Ab[(g + 8) * 133 + t];
                a[2] = Ab[g * 133 + 4 + t];  a[3] = Ab[(g + 8) * 133 + 4 + t];
                bfr[0] = uVt[(ni * 8 + g) * 132 + kk * 8 + t];
                bfr[1] = uVt[(ni * 8 + g) * 132 + kk * 8 + 4 + t];
                mma_tf32(oc[ti], a, bfr);
            }
        }
    }
    __syncthreads();

    if (tid < 32) {
        g_Jm[((size_t)chunk * BHc + bh) * 32 + tid] = mrow[tid];
        g_Jl[((size_t)chunk * BHc + bh) * 32 + tid] = lrow[tid];
    }
    float* JO = g_JO + ((size_t)chunk * BHc + bh) * 32 * 64;
    #pragma unroll
    for (int ti = 0; ti < 2; ti++) {
        int tIdx = warp + ti * 8;
        int mi = tIdx & 1, ni = tIdx >> 1;
        int q = mi * 16 + g, d = ni * 8 + 2 * t;
        *(float2*)(JO + q * 64 + d)       = make_float2(oc[ti][0], oc[ti][1]);
        *(float2*)(JO + (q + 8) * 64 + d) = make_float2(oc[ti][2], oc[ti][3]);
    }
}

// -------- joints combine --------
__global__ __launch_bounds__(256) void joints_combine() {
    __shared__ float wgt[JCH][Jc];
    __shared__ float invd[Jc];
    int bh = blockIdx.x;
    int b = bh >> 3, h = bh & 7;
    int tid = threadIdx.x;

    if (tid < Jc) {
        float mv[JCH], lv[JCH];
        float ms = -FLT_MAX;
        #pragma unroll
        for (int c = 0; c < JCH; c++) {
            mv[c] = g_Jm[((size_t)c * BHc + bh) * 32 + tid];
            lv[c] = g_Jl[((size_t)c * BHc + bh) * 32 + tid];
            ms = fmaxf(ms, mv[c]);
        }
        float den = 0.f;
        #pragma unroll
        for (int c = 0; c < JCH; c++) {
            float w = __expf(mv[c] - ms);
            wgt[c][tid] = w;
            den += lv[c] * w;
        }
        invd[tid] = 1.f / den;
    }
    __syncthreads();

    for (int i = tid; i < Jc * 64; i += 256) {
        int q = i >> 6, d = i & 63;
        float acc = 0.f;
        #pragma unroll
        for (int c = 0; c < JCH; c++)
            acc += g_JO[(((size_t)c * BHc + bh) * 32 + q) * 64 + d] * wgt[c][q];
        g_AO[((size_t)b * Nc + q) * 512 + h * 64 + d] = acc * invd[q];
    }
}

// ============ spatial attention: register-resident flash, V transposed ============
__global__ __launch_bounds__(448) void spatial_attn_reg() {
    extern __shared__ unsigned usm[];
    unsigned* uK  = usm;                 // 224*68
    unsigned* uVt = uK + 224 * 68;       // 64*228
    unsigned* uQ  = uVt + 64 * 228;      // 224*68

    int blk = blockIdx.x;
    int bh = blk >> 4, f = blk & 15;
    int b = bh >> 3, h = bh & 7;
    int tid = threadIdx.x, lane = tid & 31, warp = tid >> 5;
    int g = lane >> 2, t = lane & 3;

    const float* Krb = g_Kraw  + (size_t)bh * Nc  * 64;
    const float* Kpb = g_Krope + (size_t)bh * NSP * 64;
    const float* Vb  = g_V     + (size_t)bh * Nc  * 64;
    size_t qrow0 = (size_t)bh * Nc + Jc + f * NSc;

    for (int i = tid; i < 224 * 64; i += 448) {
        int r = i >> 6, d = i & 63;
        float kv = 0.f, vv = 0.f;
        if (r < Jc) { kv = Krb[r * 64 + d]; vv = Vb[r * 64 + d]; }
        else if (r < SKR) {
            int m = f * NSc + (r - Jc);
            kv = Kpb[(size_t)m * 64 + d];
            vv = Vb[(size_t)(Jc + m) * 64 + d];
        }
        uK[r * 68 + d]   = f2tf32(kv);
        uVt[d * 228 + r] = f2tf32(vv);
        int qr = (r < NSc) ? r : (NSc - 1);
        uQ[r * 68 + d] = f2tf32(g_Q[(qrow0 + qr) * 64 + d]);
    }
    __syncthreads();

    int qb = warp * 16;
    float m0 = -1e30f, m1 = -1e30f, l0 = 0.f, l1 = 0.f;
    float o[8][4];
    #pragma unroll
    for (int ni = 0; ni < 8; ni++)
        #pragma unroll
        for (int r = 0; r < 4; r++) o[ni][r] = 0.f;

    int src1 = (lane & ~3) | (t >> 1);
    int src2 = src1 + 2;

    #pragma unroll
    for (int pass = 0; pass < 2; pass++) {
        int kbase = pass * 112;

        unsigned aq[8][4];
        #pragma unroll
        for (int kk = 0; kk < 8; kk++) {
            const unsigned* q0p = uQ + (qb + g) * 68 + kk * 8;
            const unsigned* q1p = uQ + (qb + 8 + g) * 68 + kk * 8;
            aq[kk][0] = q0p[t];     aq[kk][1] = q1p[t];
            aq[kk][2] = q0p[4 + t]; aq[kk][3] = q1p[4 + t];
        }

        float s[14][4];
        #pragma unroll
        for (int nt = 0; nt < 14; nt++) {
            s[nt][0] = s[nt][1] = s[nt][2] = s[nt][3] = 0.f;
            int kr = kbase + nt * 8;
            #pragma unroll
            for (int kk = 0; kk < 8; kk++) {
                unsigned bfr[2];
                const unsigned* kp = uK + (kr + g) * 68 + kk * 8;
                bfr[0] = kp[t];
                bfr[1] = kp[4 + t];
                mma_tf32(s[nt], aq[kk], bfr);
            }
            if (kr + 2 * t >= SKR)     { s[nt][0] = -1e30f; s[nt][2] = -1e30f; }
            if (kr + 2 * t + 1 >= SKR) { s[nt][1] = -1e30f; s[nt][3] = -1e30f; }
        }

        float tm0 = -1e30f, tm1 = -1e30f;
        #pragma unroll
        for (int nt = 0; nt < 14; nt++) {
            tm0 = fmaxf(tm0, fmaxf(s[nt][0], s[nt][1]));
            tm1 = fmaxf(tm1, fmaxf(s[nt][2], s[nt][3]));
        }
        tm0 = fmaxf(tm0, __shfl_xor_sync(0xffffffffu, tm0, 1));
        tm0 = fmaxf(tm0, __shfl_xor_sync(0xffffffffu, tm0, 2));
        tm1 = fmaxf(tm1, __shfl_xor_sync(0xffffffffu, tm1, 1));
        tm1 = fmaxf(tm1, __shfl_xor_sync(0xffffffffu, tm1, 2));
        float mn0 = fmaxf(m0, tm0), mn1 = fmaxf(m1, tm1);
        float sc0 = __expf(m0 - mn0), sc1 = __expf(m1 - mn1);
        m0 = mn0; m1 = mn1;

        float ps0 = 0.f, ps1 = 0.f;
        #pragma unroll
        for (int nt = 0; nt < 14; nt++) {
            s[nt][0] = __expf(s[nt][0] - mn0); ps0 += s[nt][0];
            s[nt][1] = __expf(s[nt][1] - mn0); ps0 += s[nt][1];
            s[nt][2] = __expf(s[nt][2] - mn1); ps1 += s[nt][2];
            s[nt][3] = __expf(s[nt][3] - mn1); ps1 += s[nt][3];
        }
        ps0 += __shfl_xor_sync(0xffffffffu, ps0, 1);
        ps0 += __shfl_xor_sync(0xffffffffu, ps0, 2);
        ps1 += __shfl_xor_sync(0xffffffffu, ps1, 1);
        ps1 += __shfl_xor_sync(0xffffffffu, ps1, 2);
        l0 = l0 * sc0 + ps0;
        l1 = l1 * sc1 + ps1;

        #pragma unroll
        for (int ni = 0; ni < 8; ni++) {
            o[ni][0] *= sc0; o[ni][1] *= sc0;
            o[ni][2] *= sc1; o[ni][3] *= sc1;
        }

        #pragma unroll
        for (int ks = 0; ks < 14; ks++) {
            unsigned u0 = f2tf32(s[ks][0]), u1 = f2tf32(s[ks][1]);
            unsigned u2 = f2tf32(s[ks][2]), u3 = f2tf32(s[ks][3]);
            unsigned w0 = __shfl_sync(0xffffffffu, u0, src1);
            unsigned w1 = __shfl_sync(0xffffffffu, u1, src1);
            unsigned x0 = __shfl_sync(0xffffffffu, u0, src2);
            unsigned x1 = __shfl_sync(0xffffffffu, u1, src2);
            unsigned w2 = __shfl_sync(0xffffffffu, u2, src1);
            unsigned w3 = __shfl_sync(0xffffffffu, u3, src1);
            unsigned x2 = __shfl_sync(0xffffffffu, u2, src2);
            unsigned x3 = __shfl_sync(0xffffffffu, u3, src2);
            unsigned a[4];
            a[0] = (t & 1) ? w1 : w0;
            a[2] = (t & 1) ? x1 : x0;
            a[1] = (t & 1) ? w3 : w2;
            a[3] = (t & 1) ? x3 : x2;
            int kb2 = kbase + ks * 8;
            #pragma unroll
            for (int ni = 0; ni < 8; ni++) {
                unsigned bfr[2];
                bfr[0] = uVt[(ni * 8 + g) * 228 + kb2 + t];
                bfr[1] = uVt[(ni * 8 + g) * 228 + kb2 + 4 + t];
                mma_tf32(o[ni], a, bfr);
            }
        }
    }

    float inv0 = 1.f / l0, inv1 = 1.f / l1;
    int q0g = qb + g, q1g = qb + 8 + g;
    #pragma unroll
    for (int ni = 0; ni < 8; ni++) {
        int d = ni * 8 + 2 * t;
        if (q0g < NSc) {
            int n = Jc + f * NSc + q0g;
            *(float2*)(g_AO + ((size_t)b * Nc + n) * 512 + h * 64 + d) =
                make_float2(o[ni][0] * inv0, o[ni][1] * inv0);
        }
        if (q1g < NSc) {
            int n = Jc + f * NSc + q1g;
            *(float2*)(g_AO + ((size_t)b * Nc + n) * 512 + h * 64 + d) =
                make_float2(o[ni][2] * inv1, o[ni][3] * inv1);
        }
    }
}

// -------- launch --------
extern "C" void kernel_launch(void* const* d_in, const int* in_sizes, int n_in,
                              void* d_out, int out_size) {
    const float* x     = (const float*)d_in[0];
    const float* w_qkv = (const float*)d_in[1];
    const float* w_out = (const float*)d_in[2];
    const float* b_out = (const float*)d_in[3];
    const float* sinp  = (const float*)d_in[4];
    const float* cosp  = (const float*)d_in[5];
    float* out = (float*)d_out;

    void *pAO = nullptr;
    cudaGetSymbolAddress(&pAO, g_AO);

    // one-time side-stream resources (host-side only; no device memory)
    static cudaStream_t s1 = nullptr;
    static cudaEvent_t evA = nullptr, evB = nullptr;
    if (!s1) {
        cudaStreamCreateWithFlags(&s1, cudaStreamNonBlocking);
        cudaEventCreateWithFlags(&evA, cudaEventDisableTiming);
        cudaEventCreateWithFlags(&evB, cudaEventDisableTiming);
    }

    const int JSMEM = (128*68 + 64*132 + 64*36 + 128*36 + 32*133 + 256 + 96) * 4;
    const int SSMEM = (224*68 + 64*228 + 224*68) * 4;
    cudaFuncSetAttribute(joints_attn_mma,
                         cudaFuncAttributeMaxDynamicSharedMemorySize, JSMEM);
    cudaFuncSetAttribute(spatial_attn_reg,
                         cudaFuncAttributeMaxDynamicSharedMemorySize, SSMEM);

    // 1) QKV GEMM (128x256 tiles) with fused split/scale/RoPE epilogue
    dim3 g1(1536 / 256, (MROWS + 127) / 128);
    qkv_gemm_fused<<<g1, 256>>>(x, w_qkv, sinp, cosp);

    // fork: joints chain on side stream, spatial on main stream
    cudaEventRecord(evA, 0);
    cudaStreamWaitEvent(s1, evA, 0);

    joints_attn_mma<<<dim3(BHc, JCH), 256, JSMEM, s1>>>();
    joints_combine<<<BHc, 256, 0, s1>>>();
    cudaEventRecord(evB, s1);

    spatial_attn_reg<<<BHc * Fc, 448, SSMEM>>>();

    // join, then output GEMM
    cudaStreamWaitEvent(0, evB, 0);
    dim3 g2(512 / 128, (MROWS + 127) / 128);
    tgemm128<<<g2, 256>>>((const float*)pAO, w_out, b_out, out, MROWS, 512, 512);
}

// round 17
// speedup vs baseline: 1.0114x; 1.0114x over previous
#include <cuda_runtime.h>
#include <math.h>
#include <float.h>

// Problem constants
#define Bc    8
#define Fc    16
#define NSc   196
#define Jc    24
#define Hc    8
#define DHc   64
#define DIMc  512
#define ROTc  32
#define Nc    3160          // J + F*NS
#define MROWS (Bc*Nc)       // 25280
#define BHc   64            // B*H
#define NSP   3136          // F*NS
#define SKR   220           // J + NS (spatial key rows)
#define JCH   4             // joints key chunks
#define JKEYS 790           // keys per joints chunk

// -------- scratch (device globals; no runtime allocation) --------
__device__ float g_Q   [(size_t)BHc * Nc  * 64];
__device__ float g_Kraw[(size_t)BHc * Nc  * 64];
__device__ float g_Krope[(size_t)BHc * NSP * 64];
__device__ float g_V   [(size_t)BHc * Nc  * 64];
__device__ float g_AO  [(size_t)MROWS * 512];
__device__ float g_JO  [(size_t)JCH * BHc * 32 * 64];
__device__ float g_Jm  [(size_t)JCH * BHc * 32];
__device__ float g_Jl  [(size_t)JCH * BHc * 32];

// -------- tf32 helpers --------
__device__ __forceinline__ unsigned f2tf32(float x) {
    unsigned u;
    asm("cvt.rna.tf32.f32 %0, %1;" : "=r"(u) : "f"(x));
    return u;
}

__device__ __forceinline__ void mma_tf32(float* d, const unsigned* a, const unsigned* b) {
    asm volatile(
        "mma.sync.aligned.m16n8k8.row.col.f32.tf32.tf32.f32 "
        "{%0,%1,%2,%3}, {%4,%5,%6,%7}, {%8,%9}, {%0,%1,%2,%3};\n"
        : "+f"(d[0]), "+f"(d[1]), "+f"(d[2]), "+f"(d[3])
        : "r"(a[0]), "r"(a[1]), "r"(a[2]), "r"(a[3]),
          "r"(b[0]), "r"(b[1]));
}

// rope on a float4 starting at even d (pairs self-contained)
__device__ __forceinline__ void rope4(float4& v, const float* __restrict__ cosp,
                                      const float* __restrict__ sinp, int s, int d) {
    float4 cs = *(const float4*)(cosp + s * ROTc + d);
    float4 sn = *(const float4*)(sinp + s * ROTc + d);
    float x0 = v.x, x1 = v.y, x2 = v.z, x3 = v.w;
    v.x = x0 * cs.x - x1 * sn.x;
    v.y = x1 * cs.y + x0 * sn.y;
    v.z = x2 * cs.z - x3 * sn.z;
    v.w = x3 * cs.w + x2 * sn.w;
}

// ======== QKV GEMM: 128(M) x 256(N) block, 64x64 warp tile ========
// Epilogue stages C through smem and writes Q/Kraw/Krope/V coalesced (float4 along d).
__global__ __launch_bounds__(256) void qkv_gemm_fused(
        const float* __restrict__ A, const float* __restrict__ Bm,
        const float* __restrict__ sinp, const float* __restrict__ cosp) {
    extern __shared__ unsigned dynsm[];
    unsigned* As = dynsm;                    // 128*20
    unsigned* Bs = As + 128 * 20;            // 16*264
    float* stage = (float*)(Bs + 16 * 264);  // 32*264
    const int K = 512, N = 1536;

    int tid = threadIdx.x, lane = tid & 31, warp = tid >> 5;
    int wm = warp >> 2, wn = warp & 3;
    int g = lane >> 2, t = lane & 3;
    int row0 = blockIdx.y * 128;
    int col0 = blockIdx.x * 256;

    int arow = tid >> 1, aseg = (tid & 1) * 8;
    int brow = tid >> 4, bcol = (tid & 15) * 4;
    int arowg = min(row0 + arow, MROWS - 1);

    const float* Ap = A + (size_t)arowg * K + aseg;
    const float* Bp = Bm + (size_t)brow * N + col0 + bcol;

    float acc[4][8][4];
    #pragma unroll
    for (int i = 0; i < 4; i++)
        #pragma unroll
        for (int j = 0; j < 8; j++)
            #pragma unroll
            for (int r = 0; r < 4; r++) acc[i][j][r] = 0.f;

    float4 ra0 = *(const float4*)Ap, ra1 = *(const float4*)(Ap + 4);
    float4 rb[4];
    #pragma unroll
    for (int j = 0; j < 4; j++) rb[j] = *(const float4*)(Bp + j * 64);

    for (int k0 = 0; k0 < K; k0 += 16) {
        *(uint4*)&As[arow * 20 + aseg] =
            make_uint4(f2tf32(ra0.x), f2tf32(ra0.y), f2tf32(ra0.z), f2tf32(ra0.w));
        *(uint4*)&As[arow * 20 + aseg + 4] =
            make_uint4(f2tf32(ra1.x), f2tf32(ra1.y), f2tf32(ra1.z), f2tf32(ra1.w));
        #pragma unroll
        for (int j = 0; j < 4; j++)
            *(uint4*)&Bs[brow * 264 + bcol + j * 64] =
                make_uint4(f2tf32(rb[j].x), f2tf32(rb[j].y), f2tf32(rb[j].z), f2tf32(rb[j].w));
        __syncthreads();

        if (k0 + 16 < K) {
            Ap += 16;
            Bp += (size_t)16 * N;
            ra0 = *(const float4*)Ap; ra1 = *(const float4*)(Ap + 4);
            #pragma unroll
            for (int j = 0; j < 4; j++) rb[j] = *(const float4*)(Bp + j * 64);
        }

        #pragma unroll
        for (int kk = 0; kk < 16; kk += 8) {
            unsigned af[4][4], bf[8][2];
            #pragma unroll
            for (int mi = 0; mi < 4; mi++) {
                int r = wm * 64 + mi * 16;
                af[mi][0] = As[(r + g) * 20 + kk + t];
                af[mi][1] = As[(r + 8 + g) * 20 + kk + t];
                af[mi][2] = As[(r + g) * 20 + kk + 4 + t];
                af[mi][3] = As[(r + 8 + g) * 20 + kk + 4 + t];
            }
            #pragma unroll
            for (int nj = 0; nj < 8; nj++) {
                int c = wn * 64 + nj * 8 + g;
                bf[nj][0] = Bs[(kk + t) * 264 + c];
                bf[nj][1] = Bs[(kk + 4 + t) * 264 + c];
            }
            #pragma unroll
            for (int mi = 0; mi < 4; mi++)
                #pragma unroll
                for (int nj = 0; nj < 8; nj++)
                    mma_tf32(acc[mi][nj], af[mi], bf[nj]);
        }
        __syncthreads();
    }

    // ---- staged, coalesced epilogue ----
    int which = col0 >> 9;   // 0=Q, 1=K, 2=V (whole block is one region)
    #pragma unroll
    for (int chunk = 0; chunk < 4; chunk++) {
        __syncthreads();
        if (wm == (chunk >> 1)) {
            #pragma unroll
            for (int mm = 0; mm < 2; mm++) {
                int mi = (chunk & 1) * 2 + mm;
                #pragma unroll
                for (int half = 0; half < 2; half++) {
                    int lr = mm * 16 + half * 8 + g;
                    #pragma unroll
                    for (int nj = 0; nj < 8; nj++) {
                        stage[lr * 264 + wn * 64 + nj * 8 + 2 * t]     = acc[mi][nj][half * 2 + 0];
                        stage[lr * 264 + wn * 64 + nj * 8 + 2 * t + 1] = acc[mi][nj][half * 2 + 1];
                    }
                }
            }
        }
        __syncthreads();

        // 32 rows x 64 float4, row-contiguous writes
        for (int idx = tid; idx < 32 * 64; idx += 256) {
            int lr = idx >> 6, c4 = idx & 63;
            int r = row0 + chunk * 32 + lr;
            if (r >= MROWS) continue;
            int b = r / Nc, n = r - b * Nc;
            bool sp = (n >= Jc);
            int m = n - Jc;
            int s = sp ? (m % NSc) : 0;
            int cc = c4 * 4;
            int d = cc & 63;
            int h = ((col0 + cc) >> 6) & 7;
            int bh = b * 8 + h;
            float4 v = *(float4*)&stage[lr * 264 + cc];
            size_t o = ((size_t)bh * Nc + n) * 64 + d;
            if (which == 0) {
                v.x *= 0.125f; v.y *= 0.125f; v.z *= 0.125f; v.w *= 0.125f;
                if (sp && d < ROTc) rope4(v, cosp, sinp, s, d);
                *(float4*)(g_Q + o) = v;
            } else if (which == 1) {
                *(float4*)(g_Kraw + o) = v;
                if (sp) {
                    if (d < ROTc) rope4(v, cosp, sinp, s, d);
                    *(float4*)(g_Krope + ((size_t)bh * NSP + m) * 64 + d) = v;
                }
            } else {
                *(float4*)(g_V + o) = v;
            }
        }
    }
}

// ======== generic TF32 GEMM 128x128 (+bias), staged coalesced epilogue ========
__global__ __launch_bounds__(256) void tgemm128(
        const float* __restrict__ A, const float* __restrict__ Bm,
        const float* __restrict__ bias, float* __restrict__ C,
        int M, int N, int K) {
    __shared__ unsigned As[128][20];
    __shared__ unsigned Bs[16][136];
    __shared__ float stage[32][132];

    int tid = threadIdx.x, lane = tid & 31, warp = tid >> 5;
    int wm = warp >> 2, wn = warp & 3;
    int g = lane >> 2, t = lane & 3;
    int row0 = blockIdx.y * 128;
    int col0 = blockIdx.x * 128;

    int arow = tid >> 1, aseg = (tid & 1) * 8;
    int brow = tid >> 4, bseg = (tid & 15) * 8;
    int arowg = min(row0 + arow, M - 1);

    const float* Ap = A + (size_t)arowg * K + aseg;
    const float* Bp = Bm + (size_t)brow * N + col0 + bseg;

    float acc[4][4][4];
    #pragma unroll
    for (int i = 0; i < 4; i++)
        #pragma unroll
        for (int j = 0; j < 4; j++)
            #pragma unroll
            for (int r = 0; r < 4; r++) acc[i][j][r] = 0.f;

    float4 ra0 = *(const float4*)Ap,  ra1 = *(const float4*)(Ap + 4);
    float4 rb0 = *(const float4*)Bp,  rb1 = *(const float4*)(Bp + 4);

    for (int k0 = 0; k0 < K; k0 += 16) {
        *(uint4*)&As[arow][aseg] =
            make_uint4(f2tf32(ra0.x), f2tf32(ra0.y), f2tf32(ra0.z), f2tf32(ra0.w));
        *(uint4*)&As[arow][aseg + 4] =
            make_uint4(f2tf32(ra1.x), f2tf32(ra1.y), f2tf32(ra1.z), f2tf32(ra1.w));
        *(uint4*)&Bs[brow][bseg] =
            make_uint4(f2tf32(rb0.x), f2tf32(rb0.y), f2tf32(rb0.z), f2tf32(rb0.w));
        *(uint4*)&Bs[brow][bseg + 4] =
            make_uint4(f2tf32(rb1.x), f2tf32(rb1.y), f2tf32(rb1.z), f2tf32(rb1.w));
        __syncthreads();

        if (k0 + 16 < K) {
            Ap += 16;
            Bp += (size_t)16 * N;
            ra0 = *(const float4*)Ap;  ra1 = *(const float4*)(Ap + 4);
            rb0 = *(const float4*)Bp;  rb1 = *(const float4*)(Bp + 4);
        }

        #pragma unroll
        for (int kk = 0; kk < 16; kk += 8) {
            unsigned af[4][4], bf[4][2];
            #pragma unroll
            for (int mi = 0; mi < 4; mi++) {
                int r = wm * 64 + mi * 16;
                af[mi][0] = As[r + g][kk + t];
                af[mi][1] = As[r + 8 + g][kk + t];
                af[mi][2] = As[r + g][kk + 4 + t];
                af[mi][3] = As[r + 8 + g][kk + 4 + t];
            }
            #pragma unroll
            for (int nj = 0; nj < 4; nj++) {
                int c = wn * 32 + nj * 8 + g;
                bf[nj][0] = Bs[kk + t][c];
                bf[nj][1] = Bs[kk + 4 + t][c];
            }
            #pragma unroll
            for (int mi = 0; mi < 4; mi++)
                #pragma unroll
                for (int nj = 0; nj < 4; nj++)
                    mma_tf32(acc[mi][nj], af[mi], bf[nj]);
        }
        __syncthreads();
    }

    // staged, coalesced output
    #pragma unroll
    for (int chunk = 0; chunk < 4; chunk++) {
        __syncthreads();
        if (wm == (chunk >> 1)) {
            #pragma unroll
            for (int mm = 0; mm < 2; mm++) {
                int mi = (chunk & 1) * 2 + mm;
                #pragma unroll
                for (int half = 0; half < 2; half++) {
                    int lr = mm * 16 + half * 8 + g;
                    #pragma unroll
                    for (int nj = 0; nj < 4; nj++) {
                        stage[lr][wn * 32 + nj * 8 + 2 * t]     = acc[mi][nj][half * 2 + 0];
                        stage[lr][wn * 32 + nj * 8 + 2 * t + 1] = acc[mi][nj][half * 2 + 1];
                    }
                }
            }
        }
        __syncthreads();
        for (int idx = tid; idx < 32 * 32; idx += 256) {
            int lr = idx >> 5, c4 = idx & 31;
            int r = row0 + chunk * 32 + lr;
            if (r >= M) continue;
            int c = col0 + c4 * 4;
            float4 v = *(float4*)&stage[lr][c4 * 4];
            if (bias) {
                v.x += bias[c]; v.y += bias[c + 1];
                v.z += bias[c + 2]; v.w += bias[c + 3];
            }
            *(float4*)(C + (size_t)r * N + c) = v;
        }
    }
}

// ============ joints attention: split-KV flash (block per (bh, chunk)) ============
__global__ __launch_bounds__(256) void joints_attn_mma() {
    extern __shared__ float smem[];
    unsigned* uK  = (unsigned*)smem;            // 128*68
    unsigned* uVt = uK + 128 * 68;              // 64*132
    unsigned* uQ  = uVt + 64 * 132;             // 64*36
    float*    St  = (float*)(uQ + 64 * 36);     // 128*36
    unsigned* uP  = (unsigned*)(St + 128 * 36); // 32*133
    float*   red  = (float*)(uP + 32 * 133);    // 256
    float*  mrow  = red + 256;                  // 32
    float*   scl  = mrow + 32;                  // 32
    float*  lrow  = scl + 32;                   // 32

    int bh = blockIdx.x;
    int chunk = blockIdx.y;
    int kb = chunk * JKEYS;
    int tid = threadIdx.x, lane = tid & 31, warp = tid >> 5;
    int g = lane >> 2, t = lane & 3;

    const float* Kb = g_Kraw + (size_t)bh * Nc * 64;
    const float* Vb = g_V    + (size_t)bh * Nc * 64;

    if (tid < 32) { mrow[tid] = -FLT_MAX; lrow[tid] = 0.f; }

    for (int i = tid; i < 32 * 64; i += 256) {
        int q = i >> 6, d = i & 63;
        int qq = (q < Jc) ? q : (Jc - 1);
        uQ[d * 36 + q] = f2tf32(g_Q[((size_t)bh * Nc + qq) * 64 + d]);
    }

    float oc[2][4] = {{0,0,0,0},{0,0,0,0}};

    for (int c0 = 0; c0 < JKEYS; c0 += 128) {
        int kn = min(128, JKEYS - c0);
        __syncthreads();
        for (int i = tid; i < 128 * 64; i += 256) {
            int r = i >> 6, d = i & 63;
            float kv = 0.f, vv = 0.f;
            if (r < kn) {
                kv = Kb[(size_t)(kb + c0 + r) * 64 + d];
                vv = Vb[(size_t)(kb + c0 + r) * 64 + d];
            }
            uK[r * 68 + d]   = f2tf32(kv);
            uVt[d * 132 + r] = f2tf32(vv);
        }
        __syncthreads();

        for (int tIdx = warp; tIdx < 32; tIdx += 8) {
            int mi = tIdx & 7, ni = tIdx >> 3;
            if (mi * 16 >= kn + 15) continue;
            float c[4] = {0,0,0,0};
            #pragma unroll
            for (int kk = 0; kk < 8; kk++) {
                unsigned a[4], bfr[2];
                const unsigned* Ab = uK + (mi * 16) * 68 + kk * 8;
                a[0] = Ab[g * 68 + t];       a[1] = Ab[(g + 8) * 68 + t];
                a[2] = Ab[g * 68 + 4 + t];   a[3] = Ab[(g + 8) * 68 + 4 + t];
                const unsigned* Bb = uQ + (kk * 8) * 36 + ni * 8;
                bfr[0] = Bb[t * 36 + g];     bfr[1] = Bb[(4 + t) * 36 + g];
                mma_tf32(c, a, bfr);
            }
            float* Sb = St + (mi * 16) * 36 + ni * 8;
            *(float2*)(Sb + g * 36 + 2 * t)       = make_float2(c[0], c[1]);
            *(float2*)(Sb + (g + 8) * 36 + 2 * t) = make_float2(c[2], c[3]);
        }
        __syncthreads();

        {
            int q = tid & 31, s = tid >> 5;
            int j0 = s * 16, j1 = min(j0 + 16, kn);
            float lm = -FLT_MAX;
            for (int j = j0; j < j1; j++) lm = fmaxf(lm, St[j * 36 + q]);
            red[s * 32 + q] = lm;
            __syncthreads();
            float cm = red[q];
            #pragma unroll
            for (int ss = 1; ss < 8; ss++) cm = fmaxf(cm, red[ss * 32 + q]);
            float mold = mrow[q];
            float mnew = fmaxf(mold, cm);
            __syncthreads();
            float ls = 0.f;
            for (int j = j0; j < j1; j++) {
                float e = __expf(St[j * 36 + q] - mnew);
                ls += e;
                uP[q * 133 + j] = f2tf32(e);
            }
            for (int j = j1; j < j0 + 16; j++) uP[q * 133 + j] = 0u;
            red[s * 32 + q] = ls;
            __syncthreads();
            if (s == 0) {
                float tot = 0.f;
                #pragma unroll
                for (int ss = 0; ss < 8; ss++) tot += red[ss * 32 + q];
                float sc = __expf(mold - mnew);
                lrow[q] = lrow[q] * sc + tot;
                mrow[q] = mnew;
                scl[q]  = sc;
            }
        }
        __syncthreads();

        #pragma unroll
        for (int ti = 0; ti < 2; ti++) {
            int tIdx = warp + ti * 8;
            int mi = tIdx & 1, ni = tIdx >> 1;
            int q = mi * 16 + g;
            float s0 = scl[q], s1 = scl[q + 8];
            oc[ti][0] *= s0; oc[ti][1] *= s0; oc[ti][2] *= s1; oc[ti][3] *= s1;
            for (int kk = 0; kk < 16; kk++) {
                unsigned a[4], bfr[2];
                const unsigned* Ab = uP + (mi * 16) * 133 + kk * 8;
                a[0] = Ab[g * 133 + t];      a[1] = Ab[(g + 8) * 133 + t];
                a[2] = Ab[g * 133 + 4 + t];  a[3] = Ab[(g + 8) * 133 + 4 + t];
                bfr[0] = uVt[(ni * 8 + g) * 132 + kk * 8 + t];
                bfr[1] = uVt[(ni * 8 + g) * 132 + kk * 8 + 4 + t];
                mma_tf32(oc[ti], a, bfr);
            }
        }
    }
    __syncthreads();

    if (tid < 32) {
        g_Jm[((size_t)chunk * BHc + bh) * 32 + tid] = mrow[tid];
        g_Jl[((size_t)chunk * BHc + bh) * 32 + tid] = lrow[tid];
    }
    float* JO = g_JO + ((size_t)chunk * BHc + bh) * 32 * 64;
    #pragma unroll
    for (int ti = 0; ti < 2; ti++) {
        int tIdx = warp + ti * 8;
        int mi = tIdx & 1, ni = tIdx >> 1;
        int q = mi * 16 + g, d = ni * 8 + 2 * t;
        *(float2*)(JO + q * 64 + d)       = make_float2(oc[ti][0], oc[ti][1]);
        *(float2*)(JO + (q + 8) * 64 + d) = make_float2(oc[ti][2], oc[ti][3]);
    }
}

// -------- joints combine --------
__global__ __launch_bounds__(256) void joints_combine() {
    __shared__ float wgt[JCH][Jc];
    __shared__ float invd[Jc];
    int bh = blockIdx.x;
    int b = bh >> 3, h = bh & 7;
    int tid = threadIdx.x;

    if (tid < Jc) {
        float mv[JCH], lv[JCH];
        float ms = -FLT_MAX;
        #pragma unroll
        for (int c = 0; c < JCH; c++) {
            mv[c] = g_Jm[((size_t)c * BHc + bh) * 32 + tid];
            lv[c] = g_Jl[((size_t)c * BHc + bh) * 32 + tid];
            ms = fmaxf(ms, mv[c]);
        }
        float den = 0.f;
        #pragma unroll
        for (int c = 0; c < JCH; c++) {
            float w = __expf(mv[c] - ms);
            wgt[c][tid] = w;
            den += lv[c] * w;
        }
        invd[tid] = 1.f / den;
    }
    __syncthreads();

    for (int i = tid; i < Jc * 64; i += 256) {
        int q = i >> 6, d = i & 63;
        float acc = 0.f;
        #pragma unroll
        for (int c = 0; c < JCH; c++)
            acc += g_JO[(((size_t)c * BHc + bh) * 32 + q) * 64 + d] * wgt[c][q];
        g_AO[((size_t)b * Nc + q) * 512 + h * 64 + d] = acc * invd[q];
    }
}

// ============ spatial attention: register-resident flash, V transposed ============
__global__ __launch_bounds__(448) void spatial_attn_reg() {
    extern __shared__ unsigned usm[];
    unsigned* uK  = usm;                 // 224*68
    unsigned* uVt = uK + 224 * 68;       // 64*228
    unsigned* uQ  = uVt + 64 * 228;      // 224*68

    int blk = blockIdx.x;
    int bh = blk >> 4, f = blk & 15;
    int b = bh >> 3, h = bh & 7;
    int tid = threadIdx.x, lane = tid & 31, warp = tid >> 5;
    int g = lane >> 2, t = lane & 3;

    const float* Krb = g_Kraw  + (size_t)bh * Nc  * 64;
    const float* Kpb = g_Krope + (size_t)bh * NSP * 64;
    const float* Vb  = g_V     + (size_t)bh * Nc  * 64;
    size_t qrow0 = (size_t)bh * Nc + Jc + f * NSc;

    for (int i = tid; i < 224 * 64; i += 448) {
        int r = i >> 6, d = i & 63;
        float kv = 0.f, vv = 0.f;
        if (r < Jc) { kv = Krb[r * 64 + d]; vv = Vb[r * 64 + d]; }
        else if (r < SKR) {
            int m = f * NSc + (r - Jc);
            kv = Kpb[(size_t)m * 64 + d];
            vv = Vb[(size_t)(Jc + m) * 64 + d];
        }
        uK[r * 68 + d]   = f2tf32(kv);
        uVt[d * 228 + r] = f2tf32(vv);
        int qr = (r < NSc) ? r : (NSc - 1);
        uQ[r * 68 + d] = f2tf32(g_Q[(qrow0 + qr) * 64 + d]);
    }
    __syncthreads();

    int qb = warp * 16;
    float m0 = -1e30f, m1 = -1e30f, l0 = 0.f, l1 = 0.f;
    float o[8][4];
    #pragma unroll
    for (int ni = 0; ni < 8; ni++)
        #pragma unroll
        for (int r = 0; r < 4; r++) o[ni][r] = 0.f;

    int src1 = (lane & ~3) | (t >> 1);
    int src2 = src1 + 2;

    #pragma unroll
    for (int pass = 0; pass < 2; pass++) {
        int kbase = pass * 112;

        unsigned aq[8][4];
        #pragma unroll
        for (int kk = 0; kk < 8; kk++) {
            const unsigned* q0p = uQ + (qb + g) * 68 + kk * 8;
            const unsigned* q1p = uQ + (qb + 8 + g) * 68 + kk * 8;
            aq[kk][0] = q0p[t];     aq[kk][1] = q1p[t];
            aq[kk][2] = q0p[4 + t]; aq[kk][3] = q1p[4 + t];
        }

        float s[14][4];
        #pragma unroll
        for (int nt = 0; nt < 14; nt++) {
            s[nt][0] = s[nt][1] = s[nt][2] = s[nt][3] = 0.f;
            int kr = kbase + nt * 8;
            #pragma unroll
            for (int kk = 0; kk < 8; kk++) {
                unsigned bfr[2];
                const unsigned* kp = uK + (kr + g) * 68 + kk * 8;
                bfr[0] = kp[t];
                bfr[1] = kp[4 + t];
                mma_tf32(s[nt], aq[kk], bfr);
            }
            if (kr + 2 * t >= SKR)     { s[nt][0] = -1e30f; s[nt][2] = -1e30f; }
            if (kr + 2 * t + 1 >= SKR) { s[nt][1] = -1e30f; s[nt][3] = -1e30f; }
        }

        float tm0 = -1e30f, tm1 = -1e30f;
        #pragma unroll
        for (int nt = 0; nt < 14; nt++) {
            tm0 = fmaxf(tm0, fmaxf(s[nt][0], s[nt][1]));
            tm1 = fmaxf(tm1, fmaxf(s[nt][2], s[nt][3]));
        }
        tm0 = fmaxf(tm0, __shfl_xor_sync(0xffffffffu, tm0, 1));
        tm0 = fmaxf(tm0, __shfl_xor_sync(0xffffffffu, tm0, 2));
        tm1 = fmaxf(tm1, __shfl_xor_sync(0xffffffffu, tm1, 1));
        tm1 = fmaxf(tm1, __shfl_xor_sync(0xffffffffu, tm1, 2));
        float mn0 = fmaxf(m0, tm0), mn1 = fmaxf(m1, tm1);
        float sc0 = __expf(m0 - mn0), sc1 = __expf(m1 - mn1);
        m0 = mn0; m1 = mn1;

        float ps0 = 0.f, ps1 = 0.f;
        #pragma unroll
        for (int nt = 0; nt < 14; nt++) {
            s[nt][0] = __expf(s[nt][0] - mn0); ps0 += s[nt][0];
            s[nt][1] = __expf(s[nt][1] - mn0); ps0 += s[nt][1];
            s[nt][2] = __expf(s[nt][2] - mn1); ps1 += s[nt][2];
            s[nt][3] = __expf(s[nt][3] - mn1); ps1 += s[nt][3];
        }
        ps0 += __shfl_xor_sync(0xffffffffu, ps0, 1);
        ps0 += __shfl_xor_sync(0xffffffffu, ps0, 2);
        ps1 += __shfl_xor_sync(0xffffffffu, ps1, 1);
        ps1 += __shfl_xor_sync(0xffffffffu, ps1, 2);
        l0 = l0 * sc0 + ps0;
        l1 = l1 * sc1 + ps1;

        #pragma unroll
        for (int ni = 0; ni < 8; ni++) {
            o[ni][0] *= sc0; o[ni][1] *= sc0;
            o[ni][2] *= sc1; o[ni][3] *= sc1;
        }

        #pragma unroll
        for (int ks = 0; ks < 14; ks++) {
            unsigned u0 = f2tf32(s[ks][0]), u1 = f2tf32(s[ks][1]);
            unsigned u2 = f2tf32(s[ks][2]), u3 = f2tf32(s[ks][3]);
            unsigned w0 = __shfl_sync(0xffffffffu, u0, src1);
            unsigned w1 = __shfl_sync(0xffffffffu, u1, src1);
            unsigned x0 = __shfl_sync(0xffffffffu, u0, src2);
            unsigned x1 = __shfl_sync(0xffffffffu, u1, src2);
            unsigned w2 = __shfl_sync(0xffffffffu, u2, src1);
            unsigned w3 = __shfl_sync(0xffffffffu, u3, src1);
            unsigned x2 = __shfl_sync(0xffffffffu, u2, src2);
            unsigned x3 = __shfl_sync(0xffffffffu, u3, src2);
            unsigned a[4];
            a[0] = (t & 1) ? w1 : w0;
            a[2] = (t & 1) ? x1 : x0;
            a[1] = (t & 1) ? w3 : w2;
            a[3] = (t & 1) ? x3 : x2;
            int kb2 = kbase + ks * 8;
            #pragma unroll
            for (int ni = 0; ni < 8; ni++) {
                unsigned bfr[2];
                bfr[0] = uVt[(ni * 8 + g) * 228 + kb2 + t];
                bfr[1] = uVt[(ni * 8 + g) * 228 + kb2 + 4 + t];
                mma_tf32(o[ni], a, bfr);
            }
        }
    }

    float inv0 = 1.f / l0, inv1 = 1.f / l1;
    int q0g = qb + g, q1g = qb + 8 + g;
    #pragma unroll
    for (int ni = 0; ni < 8; ni++) {
        int d = ni * 8 + 2 * t;
        if (q0g < NSc) {
            int n = Jc + f * NSc + q0g;
            *(float2*)(g_AO + ((size_t)b * Nc + n) * 512 + h * 64 + d) =
                make_float2(o[ni][0] * inv0, o[ni][1] * inv0);
        }
        if (q1g < NSc) {
            int n = Jc + f * NSc + q1g;
            *(float2*)(g_AO + ((size_t)b * Nc + n) * 512 + h * 64 + d) =
                make_float2(o[ni][2] * inv1, o[ni][3] * inv1);
        }
    }
}

// -------- launch --------
extern "C" void kernel_launch(void* const* d_in, const int* in_sizes, int n_in,
                              void* d_out, int out_size) {
    const float* x     = (const float*)d_in[0];
    const float* w_qkv = (const float*)d_in[1];
    const float* w_out = (const float*)d_in[2];
    const float* b_out = (const float*)d_in[3];
    const float* sinp  = (const float*)d_in[4];
    const float* cosp  = (const float*)d_in[5];
    float* out = (float*)d_out;

    void *pAO = nullptr;
    cudaGetSymbolAddress(&pAO, g_AO);

    static cudaStream_t s1 = nullptr;
    static cudaEvent_t evA = nullptr, evB = nullptr;
    if (!s1) {
        cudaStreamCreateWithFlags(&s1, cudaStreamNonBlocking);
        cudaEventCreateWithFlags(&evA, cudaEventDisableTiming);
        cudaEventCreateWithFlags(&evB, cudaEventDisableTiming);
    }

    const int QSMEM = (128 * 20 + 16 * 264) * 4 + 32 * 264 * 4;
    const int JSMEM = (128*68 + 64*132 + 64*36 + 128*36 + 32*133 + 256 + 96) * 4;
    const int SSMEM = (224*68 + 64*228 + 224*68) * 4;
    cudaFuncSetAttribute(qkv_gemm_fused,
                         cudaFuncAttributeMaxDynamicSharedMemorySize, QSMEM);
    cudaFuncSetAttribute(joints_attn_mma,
                         cudaFuncAttributeMaxDynamicSharedMemorySize, JSMEM);
    cudaFuncSetAttribute(spatial_attn_reg,
                         cudaFuncAttributeMaxDynamicSharedMemorySize, SSMEM);

    // 1) QKV GEMM (128x256) with fused, staged split/scale/RoPE epilogue
    dim3 g1(1536 / 256, (MROWS + 127) / 128);
    qkv_gemm_fused<<<g1, 256, QSMEM>>>(x, w_qkv, sinp, cosp);

    // fork: joints chain on side stream, spatial on main stream
    cudaEventRecord(evA, 0);
    cudaStreamWaitEvent(s1, evA, 0);

    joints_attn_mma<<<dim3(BHc, JCH), 256, JSMEM, s1>>>();
    joints_combine<<<BHc, 256, 0, s1>>>();
    cudaEventRecord(evB, s1);

    spatial_attn_reg<<<BHc * Fc, 448, SSMEM>>>();

    // join, then output GEMM
    cudaStreamWaitEvent(0, evB, 0);
    dim3 g2(512 / 128, (MROWS + 127) / 128);
    tgemm128<<<g2, 256>>>((const float*)pAO, w_out, b_out, out, MROWS, 512, 512);
}